// round 4
// baseline (speedup 1.0000x reference)
#include <cuda_runtime.h>
#include <cuda_bf16.h>
#include <cstddef>

// Sampler_51419348468365
//
// out = stop_gradient(1 - y) + y  ==  1.0f value-wise (y = softmax in (0,1);
// fp32 rounding <= ~1.2e-7, tolerance 1e-3). Output is a constant-1.0f fill.
//
// R3: replace the kernel node with a graph MEMSET node. 1.0f == 0x3F800000,
// a 32-bit pattern, so cuMemsetD32Async (stream-captured -> memset node)
// performs the whole job on the driver's fill path with no SM launch ramp.
// Driver entry point resolved via cudaGetDriverEntryPoint (no -lcuda link
// needed). Fallback: the proven STG.128 kernel.

typedef int (*PFN_cuMemsetD32Async)(unsigned long long dstDevice,
                                    unsigned int ui, size_t N, void* hStream);

static PFN_cuMemsetD32Async resolve_memset_d32() {
    static PFN_cuMemsetD32Async fn = nullptr;
    static bool tried = false;
    if (!tried) {
        tried = true;
        void* p = nullptr;
        cudaDriverEntryPointQueryResult st;
        if (cudaGetDriverEntryPoint("cuMemsetD32Async", &p,
                                    cudaEnableDefault, &st) == cudaSuccess &&
            st == cudaDriverEntryPointSuccess) {
            fn = (PFN_cuMemsetD32Async)p;
        }
    }
    return fn;
}

__global__ __launch_bounds__(256, 1)
void Sampler_fill_ones(float4* __restrict__ out4, int n4,
                       float* __restrict__ out_tail, int n_total) {
    int i = blockIdx.x * 256 + threadIdx.x;
    const float4 ones = make_float4(1.0f, 1.0f, 1.0f, 1.0f);
    if (i < n4) out4[i] = ones;
    int t = i - n4;
    if (t >= 0 && 4 * n4 + t < n_total) out_tail[4 * n4 + t] = 1.0f;
}

extern "C" void kernel_launch(void* const* d_in, const int* in_sizes, int n_in,
                              void* d_out, int out_size) {
    (void)d_in; (void)in_sizes; (void)n_in;

    PFN_cuMemsetD32Async fn = resolve_memset_d32();
    if (fn) {
        // 0x3F800000 == 1.0f; legacy default stream (0) matches the
        // harness's capture stream (same as <<<>>> launches).
        fn((unsigned long long)d_out, 0x3F800000u, (size_t)out_size, nullptr);
        return;
    }

    // Fallback: kernel fill (R1 variant).
    float* out = (float*)d_out;
    int n4 = out_size / 4;
    int total_threads = n4 + (out_size - 4 * n4);
    if (total_threads < 1) total_threads = 1;
    int blocks = (total_threads + 255) / 256;
    Sampler_fill_ones<<<blocks, 256>>>((float4*)out, n4, out, out_size);
}